// round 1
// baseline (speedup 1.0000x reference)
#include <cuda_runtime.h>

#define SLEN 4096
#define NBATCH 8
#define TOK (NBATCH*SLEN)
#define EMB 1024
#define HD 64
#define HALF 32

// Scratch for projected q/k/v (device globals: allocation-free rule)
__device__ float g_K[TOK*HD];
__device__ float g_Q[TOK*HD];
__device__ float g_V[TOK*HD];

// ---------- packed f32x2 helpers (Blackwell-only, PTX required) ----------
__device__ __forceinline__ unsigned long long pk2(float lo, float hi) {
    unsigned long long r;
    asm("mov.b64 %0, {%1, %2};" : "=l"(r) : "f"(lo), "f"(hi));
    return r;
}
__device__ __forceinline__ void upk2(unsigned long long v, float& lo, float& hi) {
    asm("mov.b64 {%0, %1}, %2;" : "=f"(lo), "=f"(hi) : "l"(v));
}
__device__ __forceinline__ unsigned long long fma2(unsigned long long a, unsigned long long b, unsigned long long c) {
    unsigned long long d;
    asm("fma.rn.f32x2 %0, %1, %2, %3;" : "=l"(d) : "l"(a), "l"(b), "l"(c));
    return d;
}
__device__ __forceinline__ unsigned long long mul2(unsigned long long a, unsigned long long b) {
    unsigned long long d;
    asm("mul.rn.f32x2 %0, %1, %2;" : "=l"(d) : "l"(a), "l"(b));
    return d;
}
__device__ __forceinline__ unsigned long long add2(unsigned long long a, unsigned long long b) {
    unsigned long long d;
    asm("add.rn.f32x2 %0, %1, %2;" : "=l"(d) : "l"(a), "l"(b));
    return d;
}

// =========================================================================
// Projection kernel: H = tanh(X @ W1 + b1); out = H @ W2, for k/q/v fused.
// Block = 64 tokens, 256 threads. Weight tiles staged in smem (reuse x64).
// Phase-1 smem (Xs,Ws) unions with phase-2 (Hs); W2s loaded once up front.
// =========================================================================
__global__ __launch_bounds__(256) void proj_kernel(
    const float* __restrict__ x,
    const float* __restrict__ wk1, const float* __restrict__ bk1, const float* __restrict__ wk2,
    const float* __restrict__ wq1, const float* __restrict__ bq1, const float* __restrict__ wq2,
    const float* __restrict__ wv1, const float* __restrict__ bv1, const float* __restrict__ wv2)
{
    __shared__ __align__(16) float smem[12288];  // exactly 48 KB
    float* Xs  = smem;          // [64][33] = 2112 floats   (phase 1)
    float* Ws  = smem + 2112;   // [32][96] = 3072 floats   (phase 1, ends 5184)
    float* Hs  = smem;          // [64][96] = 6144 floats   (phase 2, unions Xs/Ws)
    float* W2s = smem + 6144;   // [3][32][64] = 6144 floats (disjoint from phase 1)

    const int tid  = threadIdx.x;
    const int tok0 = blockIdx.x * 64;

    // Load W2 (k|q|v) once; safe: region [6144,12288) untouched by phase 1.
    {
        const float* w2p0 = wk2; const float* w2p1 = wq2; const float* w2p2 = wv2;
        for (int idx = tid; idx < 3*32*64; idx += 256) {
            int p = idx >> 11, rem = idx & 2047;
            const float* w2 = (p == 0) ? w2p0 : ((p == 1) ? w2p1 : w2p2);
            W2s[idx] = w2[rem];
        }
    }

    const int tx = tid & 15;   // 16 column-groups of 6 cols
    const int ty = tid >> 4;   // 16 token-groups of 4 tokens

    unsigned long long acc2[4][3];
#pragma unroll
    for (int i = 0; i < 4; i++)
#pragma unroll
        for (int j = 0; j < 3; j++) acc2[i][j] = 0ull;

    for (int k0 = 0; k0 < EMB; k0 += 32) {
        __syncthreads();
        // stage X tile [64 tokens][32 k] (pitch 33: conflict-free)
        for (int idx = tid; idx < 64*32; idx += 256) {
            int t = idx >> 5, kk = idx & 31;
            Xs[t*33 + kk] = x[(long long)(tok0 + t)*EMB + k0 + kk];
        }
        // stage W1 tile [32 k][96 cols]  (cols: 0-31 k, 32-63 q, 64-95 v)
        for (int idx = tid; idx < 32*96; idx += 256) {
            int kk = idx / 96, c = idx % 96;
            int p = c >> 5, h = c & 31;
            const float* w1 = (p == 0) ? wk1 : ((p == 1) ? wq1 : wv1);
            Ws[kk*96 + c] = w1[(k0 + kk)*HALF + h];
        }
        __syncthreads();

#pragma unroll
        for (int kk = 0; kk < 32; kk++) {
            unsigned long long a2[4];
#pragma unroll
            for (int i = 0; i < 4; i++) {
                float a = Xs[(ty*4 + i)*33 + kk];
                a2[i] = pk2(a, a);
            }
            unsigned long long b2[3];
#pragma unroll
            for (int j = 0; j < 3; j++)
                b2[j] = *(const unsigned long long*)&Ws[kk*96 + tx*6 + 2*j];
#pragma unroll
            for (int i = 0; i < 4; i++)
#pragma unroll
                for (int j = 0; j < 3; j++)
                    acc2[i][j] = fma2(a2[i], b2[j], acc2[i][j]);
        }
    }
    __syncthreads();

    // bias + tanh -> Hs (overwrites Xs/Ws; all reads complete)
#pragma unroll
    for (int i = 0; i < 4; i++) {
#pragma unroll
        for (int j = 0; j < 3; j++) {
            float lo, hi;
            upk2(acc2[i][j], lo, hi);
            int c0 = tx*6 + 2*j;            // even; pair never crosses a proj boundary
            int p0 = c0 >> 5, h0 = c0 & 31;
            const float* b1 = (p0 == 0) ? bk1 : ((p0 == 1) ? bq1 : bv1);
            lo = tanhf(lo + b1[h0]);
            hi = tanhf(hi + b1[h0 + 1]);
            Hs[(ty*4 + i)*96 + c0]     = lo;
            Hs[(ty*4 + i)*96 + c0 + 1] = hi;
        }
    }
    __syncthreads();

    // Phase 2: out[t, p, h] = sum_j Hs[t, p*32+j] * W2s[p][j][h]
    for (int idx = tid; idx < 64*96; idx += 256) {
        int t = idx / 96, cp = idx % 96;
        int p = cp >> 5, hp = cp & 31;     // hp indexes h-pairs (h = 2*hp)
        unsigned long long acc = 0ull;
#pragma unroll
        for (int j = 0; j < 32; j++) {
            float a = Hs[t*96 + p*32 + j];
            unsigned long long b = *(const unsigned long long*)&W2s[p*2048 + j*64 + 2*hp];
            acc = fma2(pk2(a, a), b, acc);
        }
        float lo, hi;
        upk2(acc, lo, hi);
        float* gout = (p == 0) ? g_K : ((p == 1) ? g_Q : g_V);
        long long o = (long long)(tok0 + t)*HD + 2*hp;
        gout[o]     = lo;
        gout[o + 1] = hi;
    }
}

// =========================================================================
// Causal flash attention, fp32 + f32x2.
// Block = 64 queries (one qt tile), 256 threads.
// Thread (ql, g): query ql, key-quarter g (16 keys of each 64-key tile).
// Partial softmax merged across the 4 adjacent lanes via shfl.xor.
// Heavy (large-qt) blocks scheduled first for wave balance.
// =========================================================================
__global__ __launch_bounds__(256, 1) void attn_kernel(float* __restrict__ out)
{
    __shared__ __align__(16) float Kt[64*66];  // transposed: Kt[d][r], pitch 66 (even)
    __shared__ __align__(16) float Vs[64*64];  // Vs[r][d]

    const int tid = threadIdx.x;
    const int g   = tid & 3;    // key-quarter group (lane bits 0-1)
    const int ql  = tid >> 2;   // local query 0..63
    const int bid = blockIdx.x;
    const int b   = bid & 7;
    const int qt  = 63 - (bid >> 3);   // heavy diagonal blocks first
    const int q   = qt*64 + ql;
    const long long qoff = ((long long)b*SLEN + q)*HD;

    float qreg[64];
#pragma unroll
    for (int d = 0; d < 64; d++) qreg[d] = g_Q[qoff + d] * 0.125f;  // 1/sqrt(64)

    unsigned long long o2[32];
#pragma unroll
    for (int j = 0; j < 32; j++) o2[j] = 0ull;
    float m = -1e30f, l = 0.f;

    const int r0 = g*16;

    for (int kt = 0; kt <= qt; kt++) {
        const int kb = kt*64;
        __syncthreads();
        {
            const long long base = ((long long)b*SLEN + kb)*HD;
            for (int idx = tid; idx < 64*64; idx += 256) {
                int r = idx >> 6, d = idx & 63;
                Kt[d*66 + r] = g_K[base + idx];   // idx = r*64 + d
                Vs[idx]      = g_V[base + idx];
            }
        }
        __syncthreads();

        // --- s = q . K^T (packed over key pairs) ---
        unsigned long long s2[8];
#pragma unroll
        for (int j = 0; j < 8; j++) s2[j] = 0ull;
#pragma unroll
        for (int d = 0; d < 64; d++) {
            unsigned long long qq = pk2(qreg[d], qreg[d]);
            const unsigned long long* kp = (const unsigned long long*)&Kt[d*66 + r0];
#pragma unroll
            for (int j = 0; j < 8; j++) s2[j] = fma2(qq, kp[j], s2[j]);
        }
        float s[16];
#pragma unroll
        for (int j = 0; j < 8; j++) upk2(s2[j], s[2*j], s[2*j+1]);

        if (kt == qt) {  // only the diagonal tile needs masking (uniform branch)
#pragma unroll
            for (int i = 0; i < 16; i++)
                if (kb + r0 + i > q) s[i] = -1e30f;
        }

        // --- online softmax update ---
        float mn = m;
#pragma unroll
        for (int i = 0; i < 16; i++) mn = fmaxf(mn, s[i]);
        float c = __expf(m - mn);
        m = mn;
        float p[16], ps = 0.f;
#pragma unroll
        for (int i = 0; i < 16; i++) { p[i] = __expf(s[i] - m); ps += p[i]; }
        l = l*c + ps;
        unsigned long long cc = pk2(c, c);
#pragma unroll
        for (int j = 0; j < 32; j++) o2[j] = mul2(o2[j], cc);

        // --- o += p . V (packed over dim pairs) ---
#pragma unroll
        for (int i = 0; i < 16; i++) {
            unsigned long long pp = pk2(p[i], p[i]);
            const unsigned long long* vp = (const unsigned long long*)&Vs[(r0 + i)*64];
#pragma unroll
            for (int j = 0; j < 32; j++) o2[j] = fma2(pp, vp[j], o2[j]);
        }
    }

    // --- merge the 4 key-quarter partials (adjacent lanes) ---
    float mg = m;
#pragma unroll
    for (int off = 1; off < 4; off <<= 1)
        m = fmaxf(m, __shfl_xor_sync(0xffffffffu, m, off));
    float w  = __expf(mg - m);   // fully-masked partials: exp(-1e30 - m) -> 0
    float lw = l * w;
#pragma unroll
    for (int off = 1; off < 4; off <<= 1)
        lw += __shfl_xor_sync(0xffffffffu, lw, off);

    unsigned long long ww = pk2(w, w);
#pragma unroll
    for (int j = 0; j < 32; j++) {
        o2[j] = mul2(o2[j], ww);
#pragma unroll
        for (int off = 1; off < 4; off <<= 1)
            o2[j] = add2(o2[j], __shfl_xor_sync(0xffffffffu, o2[j], off));
    }

    if (g == 0) {
        float inv = 1.0f / lw;
        float2* outp = (float2*)(out + qoff);
#pragma unroll
        for (int j = 0; j < 32; j++) {
            float lo, hi;
            upk2(o2[j], lo, hi);
            outp[j] = make_float2(lo*inv, hi*inv);
        }
    }
}

extern "C" void kernel_launch(void* const* d_in, const int* in_sizes, int n_in,
                              void* d_out, int out_size)
{
    const float* x   = (const float*)d_in[0];
    const float* wk1 = (const float*)d_in[1];
    const float* bk1 = (const float*)d_in[2];
    const float* wk2 = (const float*)d_in[3];
    const float* wq1 = (const float*)d_in[4];
    const float* bq1 = (const float*)d_in[5];
    const float* wq2 = (const float*)d_in[6];
    const float* wv1 = (const float*)d_in[7];
    const float* bv1 = (const float*)d_in[8];
    const float* wv2 = (const float*)d_in[9];

    proj_kernel<<<TOK/64, 256>>>(x, wk1, bk1, wk2, wq1, bq1, wq2, wv1, bv1, wv2);
    attn_kernel<<<NBATCH * (SLEN/64), 256>>>((float*)d_out);
}

// round 2
// speedup vs baseline: 2.4382x; 2.4382x over previous
#include <cuda_runtime.h>

#define SLEN 4096
#define NBATCH 8
#define TOK (NBATCH*SLEN)
#define EMB 1024
#define HD 64
#define HALF 32

// Scratch for projected q/k/v (device globals: allocation-free rule)
__device__ float g_K[TOK*HD];
__device__ float g_Q[TOK*HD];
__device__ float g_V[TOK*HD];

// ---------- packed f32x2 helpers (Blackwell-only, PTX required) ----------
__device__ __forceinline__ unsigned long long pk2(float lo, float hi) {
    unsigned long long r;
    asm("mov.b64 %0, {%1, %2};" : "=l"(r) : "f"(lo), "f"(hi));
    return r;
}
__device__ __forceinline__ void upk2(unsigned long long v, float& lo, float& hi) {
    asm("mov.b64 {%0, %1}, %2;" : "=f"(lo), "=f"(hi) : "l"(v));
}
__device__ __forceinline__ unsigned long long fma2(unsigned long long a, unsigned long long b, unsigned long long c) {
    unsigned long long d;
    asm("fma.rn.f32x2 %0, %1, %2, %3;" : "=l"(d) : "l"(a), "l"(b), "l"(c));
    return d;
}
__device__ __forceinline__ unsigned long long mul2(unsigned long long a, unsigned long long b) {
    unsigned long long d;
    asm("mul.rn.f32x2 %0, %1, %2;" : "=l"(d) : "l"(a), "l"(b));
    return d;
}

// =========================================================================
// Projection kernel: H = tanh(X @ W1 + b1); out = H @ W2, for k/q/v fused.
// (unchanged from R1 — not the bottleneck)
// =========================================================================
__global__ __launch_bounds__(256) void proj_kernel(
    const float* __restrict__ x,
    const float* __restrict__ wk1, const float* __restrict__ bk1, const float* __restrict__ wk2,
    const float* __restrict__ wq1, const float* __restrict__ bq1, const float* __restrict__ wq2,
    const float* __restrict__ wv1, const float* __restrict__ bv1, const float* __restrict__ wv2)
{
    __shared__ __align__(16) float smem[12288];  // exactly 48 KB
    float* Xs  = smem;          // [64][33] (phase 1)
    float* Ws  = smem + 2112;   // [32][96] (phase 1)
    float* Hs  = smem;          // [64][96] (phase 2, unions Xs/Ws)
    float* W2s = smem + 6144;   // [3][32][64]

    const int tid  = threadIdx.x;
    const int tok0 = blockIdx.x * 64;

    {
        const float* w2p0 = wk2; const float* w2p1 = wq2; const float* w2p2 = wv2;
        for (int idx = tid; idx < 3*32*64; idx += 256) {
            int p = idx >> 11, rem = idx & 2047;
            const float* w2 = (p == 0) ? w2p0 : ((p == 1) ? w2p1 : w2p2);
            W2s[idx] = w2[rem];
        }
    }

    const int tx = tid & 15;
    const int ty = tid >> 4;

    unsigned long long acc2[4][3];
#pragma unroll
    for (int i = 0; i < 4; i++)
#pragma unroll
        for (int j = 0; j < 3; j++) acc2[i][j] = 0ull;

    for (int k0 = 0; k0 < EMB; k0 += 32) {
        __syncthreads();
        for (int idx = tid; idx < 64*32; idx += 256) {
            int t = idx >> 5, kk = idx & 31;
            Xs[t*33 + kk] = x[(long long)(tok0 + t)*EMB + k0 + kk];
        }
        for (int idx = tid; idx < 32*96; idx += 256) {
            int kk = idx / 96, c = idx % 96;
            int p = c >> 5, h = c & 31;
            const float* w1 = (p == 0) ? wk1 : ((p == 1) ? wq1 : wv1);
            Ws[kk*96 + c] = w1[(k0 + kk)*HALF + h];
        }
        __syncthreads();

#pragma unroll
        for (int kk = 0; kk < 32; kk++) {
            unsigned long long a2[4];
#pragma unroll
            for (int i = 0; i < 4; i++) {
                float a = Xs[(ty*4 + i)*33 + kk];
                a2[i] = pk2(a, a);
            }
            unsigned long long b2[3];
#pragma unroll
            for (int j = 0; j < 3; j++)
                b2[j] = *(const unsigned long long*)&Ws[kk*96 + tx*6 + 2*j];
#pragma unroll
            for (int i = 0; i < 4; i++)
#pragma unroll
                for (int j = 0; j < 3; j++)
                    acc2[i][j] = fma2(a2[i], b2[j], acc2[i][j]);
        }
    }
    __syncthreads();

#pragma unroll
    for (int i = 0; i < 4; i++) {
#pragma unroll
        for (int j = 0; j < 3; j++) {
            float lo, hi;
            upk2(acc2[i][j], lo, hi);
            int c0 = tx*6 + 2*j;
            int p0 = c0 >> 5, h0 = c0 & 31;
            const float* b1 = (p0 == 0) ? bk1 : ((p0 == 1) ? bq1 : bv1);
            lo = tanhf(lo + b1[h0]);
            hi = tanhf(hi + b1[h0 + 1]);
            Hs[(ty*4 + i)*96 + c0]     = lo;
            Hs[(ty*4 + i)*96 + c0 + 1] = hi;
        }
    }
    __syncthreads();

    for (int idx = tid; idx < 64*96; idx += 256) {
        int t = idx / 96, cp = idx % 96;
        int p = cp >> 5, hp = cp & 31;
        unsigned long long acc = 0ull;
#pragma unroll
        for (int j = 0; j < 32; j++) {
            float a = Hs[t*96 + p*32 + j];
            unsigned long long b = *(const unsigned long long*)&W2s[p*2048 + j*64 + 2*hp];
            acc = fma2(pk2(a, a), b, acc);
        }
        float lo, hi;
        upk2(acc, lo, hi);
        float* gout = (p == 0) ? g_K : ((p == 1) ? g_Q : g_V);
        long long o = (long long)(tok0 + t)*HD + 2*hp;
        gout[o]     = lo;
        gout[o + 1] = hi;
    }
}

// =========================================================================
// Causal flash attention v2: conflict-free LDS layouts.
//   Block = 64 queries, 256 threads. Thread (ql, g): query ql; g in 0..3.
//   QK: thread g owns interleaved keys {4i+g}. K row-major, pitch 68
//       (rows 16B-apart mod 128) -> all LDS.128 conflict-free w/ broadcast.
//   PV: thread g owns output dims [8g,8g+8) u [32+8g,32+8g+8); all 4 lanes
//       read the SAME V row at 32B-apart chunks -> conflict-free.
//   P exchanged via a row aliased over Ks (same-warp producers -> syncwarp).
// =========================================================================
__global__ __launch_bounds__(256, 1) void attn_kernel(float* __restrict__ out)
{
    __shared__ __align__(16) float Ks[64*68];   // keys, pitch 68; aliased as P after QK
    __shared__ __align__(16) float Vs[64*68];   // values, pitch 68

    const int tid = threadIdx.x;
    const int g   = tid & 3;
    const int ql  = tid >> 2;
    const int bid = blockIdx.x;
    const int b   = bid & 7;
    const int qt  = 63 - (bid >> 3);            // heavy diagonal blocks first
    const int q   = qt*64 + ql;
    const long long qoff = ((long long)b*SLEN + q)*HD;

    // q packed into f32x2 pairs, prescaled by 1/sqrt(64)
    unsigned long long q2[32];
    {
        const unsigned long long* qp = (const unsigned long long*)(g_Q + qoff);
        unsigned long long sc = pk2(0.125f, 0.125f);
#pragma unroll
        for (int j = 0; j < 32; j++) q2[j] = mul2(qp[j], sc);
    }

    unsigned long long o2[8];   // 16 output dims (lane-owned), packed
#pragma unroll
    for (int j = 0; j < 8; j++) o2[j] = 0ull;
    float m = -1e30f, l = 0.f;

    for (int kt = 0; kt <= qt; kt++) {
        __syncthreads();   // previous tile's Vs/P reads done
        {
            const long long base = ((long long)b*SLEN + (long long)kt*64)*HD;
            const float4* gk = (const float4*)(g_K + base);
            const float4* gv = (const float4*)(g_V + base);
#pragma unroll
            for (int it = 0; it < 4; it++) {
                int idx = tid + it*256;          // 1024 float4 slots
                int r = idx >> 4, f = idx & 15;
                *(float4*)&Ks[r*68 + f*4] = gk[idx];
                *(float4*)&Vs[r*68 + f*4] = gv[idx];
            }
        }
        __syncthreads();

        // ---- QK: s[i] for keys k = 4i+g, accumulated as d-pairs ----
        unsigned long long s2[16];
#pragma unroll
        for (int i = 0; i < 16; i++) s2[i] = 0ull;

#pragma unroll
        for (int i4 = 0; i4 < 4; i4++) {
            const float* r0 = &Ks[(16*i4 + g)*68];
#pragma unroll
            for (int j = 0; j < 16; j++) {
#pragma unroll
                for (int c = 0; c < 4; c++) {
                    // key = 16*i4 + 4*c + g  -> row offset (16*i4+g)*68 + c*272
                    ulonglong2 kv = *(const ulonglong2*)(r0 + c*272 + 4*j);
                    s2[i4*4 + c] = fma2(q2[2*j],   kv.x, s2[i4*4 + c]);
                    s2[i4*4 + c] = fma2(q2[2*j+1], kv.y, s2[i4*4 + c]);
                }
            }
        }

        float s[16];
#pragma unroll
        for (int i = 0; i < 16; i++) {
            float lo, hi; upk2(s2[i], lo, hi); s[i] = lo + hi;
        }

        if (kt == qt) {   // only diagonal tile masks (uniform branch)
#pragma unroll
            for (int i = 0; i < 16; i++)
                if (kt*64 + 4*i + g > q) s[i] = -1e30f;
        }

        // ---- online softmax; m merged across the 4 lanes of each query ----
        float mn = m;
#pragma unroll
        for (int i = 0; i < 16; i++) mn = fmaxf(mn, s[i]);
        mn = fmaxf(mn, __shfl_xor_sync(0xffffffffu, mn, 1));
        mn = fmaxf(mn, __shfl_xor_sync(0xffffffffu, mn, 2));
        float c = __expf(m - mn);
        m = mn;
        float p[16], ps = 0.f;
#pragma unroll
        for (int i = 0; i < 16; i++) { p[i] = __expf(s[i] - m); ps += p[i]; }
        l = l*c + ps;   // l stays lane-partial; merged at the end
        unsigned long long cc = pk2(c, c);
#pragma unroll
        for (int j = 0; j < 8; j++) o2[j] = mul2(o2[j], cc);

        __syncthreads();            // all warps done reading Ks
        // ---- publish P over the dead Ks region (own-warp consumers only) ----
        float* Ps = Ks;
#pragma unroll
        for (int i = 0; i < 16; i++) Ps[ql*68 + 4*i + g] = p[i];
        __syncwarp();

        // ---- PV: full key sweep over lane-owned dim chunks ----
        const float* vbase = &Vs[8*g];
        const float* prow  = &Ks[ql*68];
#pragma unroll 8
        for (int k = 0; k < 64; k++) {
            float pk = prow[k];
            unsigned long long pp = pk2(pk, pk);
            const unsigned long long* v0 = (const unsigned long long*)(vbase + k*68);
            const unsigned long long* v1 = (const unsigned long long*)(vbase + k*68 + 32);
            o2[0] = fma2(pp, v0[0], o2[0]);
            o2[1] = fma2(pp, v0[1], o2[1]);
            o2[2] = fma2(pp, v0[2], o2[2]);
            o2[3] = fma2(pp, v0[3], o2[3]);
            o2[4] = fma2(pp, v1[0], o2[4]);
            o2[5] = fma2(pp, v1[1], o2[5]);
            o2[6] = fma2(pp, v1[2], o2[6]);
            o2[7] = fma2(pp, v1[3], o2[7]);
        }
    }

    // ---- merge l across the 4 lanes; each lane writes its own dims ----
    float lw = l;
    lw += __shfl_xor_sync(0xffffffffu, lw, 1);
    lw += __shfl_xor_sync(0xffffffffu, lw, 2);
    float inv = 1.0f / lw;
    unsigned long long ii = pk2(inv, inv);
    float* o0 = out + qoff + 8*g;
#pragma unroll
    for (int j = 0; j < 4; j++) {
        float lo, hi;
        unsigned long long v = mul2(o2[j], ii);
        upk2(v, lo, hi);
        *(float2*)(o0 + 2*j) = make_float2(lo, hi);
        v = mul2(o2[4+j], ii);
        upk2(v, lo, hi);
        *(float2*)(o0 + 32 + 2*j) = make_float2(lo, hi);
    }
}

extern "C" void kernel_launch(void* const* d_in, const int* in_sizes, int n_in,
                              void* d_out, int out_size)
{
    const float* x   = (const float*)d_in[0];
    const float* wk1 = (const float*)d_in[1];
    const float* bk1 = (const float*)d_in[2];
    const float* wk2 = (const float*)d_in[3];
    const float* wq1 = (const float*)d_in[4];
    const float* bq1 = (const float*)d_in[5];
    const float* wq2 = (const float*)d_in[6];
    const float* wv1 = (const float*)d_in[7];
    const float* bv1 = (const float*)d_in[8];
    const float* wv2 = (const float*)d_in[9];

    proj_kernel<<<TOK/64, 256>>>(x, wk1, bk1, wk2, wq1, bq1, wq2, wv1, bv1, wv2);
    attn_kernel<<<NBATCH * (SLEN/64), 256>>>((float*)d_out);
}

// round 3
// speedup vs baseline: 4.1990x; 1.7222x over previous
#include <cuda_runtime.h>

#define SLEN 4096
#define NBATCH 8
#define TOK (NBATCH*SLEN)
#define EMB 1024
#define HD 64
#define HALF 32

// Scratch for projected q/k/v (device globals: allocation-free rule)
__device__ float g_K[TOK*HD];
__device__ float g_Q[TOK*HD];
__device__ float g_V[TOK*HD];

// ---------- packed f32x2 helpers (Blackwell-only, PTX required) ----------
__device__ __forceinline__ unsigned long long pk2(float lo, float hi) {
    unsigned long long r;
    asm("mov.b64 %0, {%1, %2};" : "=l"(r) : "f"(lo), "f"(hi));
    return r;
}
__device__ __forceinline__ void upk2(unsigned long long v, float& lo, float& hi) {
    asm("mov.b64 {%0, %1}, %2;" : "=f"(lo), "=f"(hi) : "l"(v));
}
__device__ __forceinline__ unsigned long long fma2(unsigned long long a, unsigned long long b, unsigned long long c) {
    unsigned long long d;
    asm("fma.rn.f32x2 %0, %1, %2, %3;" : "=l"(d) : "l"(a), "l"(b), "l"(c));
    return d;
}
__device__ __forceinline__ unsigned long long mul2(unsigned long long a, unsigned long long b) {
    unsigned long long d;
    asm("mul.rn.f32x2 %0, %1, %2;" : "=l"(d) : "l"(a), "l"(b));
    return d;
}

// =========================================================================
// Projection kernel (unchanged — not the current bottleneck)
// =========================================================================
__global__ __launch_bounds__(256) void proj_kernel(
    const float* __restrict__ x,
    const float* __restrict__ wk1, const float* __restrict__ bk1, const float* __restrict__ wk2,
    const float* __restrict__ wq1, const float* __restrict__ bq1, const float* __restrict__ wq2,
    const float* __restrict__ wv1, const float* __restrict__ bv1, const float* __restrict__ wv2)
{
    __shared__ __align__(16) float smem[12288];
    float* Xs  = smem;
    float* Ws  = smem + 2112;
    float* Hs  = smem;
    float* W2s = smem + 6144;

    const int tid  = threadIdx.x;
    const int tok0 = blockIdx.x * 64;

    {
        const float* w2p0 = wk2; const float* w2p1 = wq2; const float* w2p2 = wv2;
        for (int idx = tid; idx < 3*32*64; idx += 256) {
            int p = idx >> 11, rem = idx & 2047;
            const float* w2 = (p == 0) ? w2p0 : ((p == 1) ? w2p1 : w2p2);
            W2s[idx] = w2[rem];
        }
    }

    const int tx = tid & 15;
    const int ty = tid >> 4;

    unsigned long long acc2[4][3];
#pragma unroll
    for (int i = 0; i < 4; i++)
#pragma unroll
        for (int j = 0; j < 3; j++) acc2[i][j] = 0ull;

    for (int k0 = 0; k0 < EMB; k0 += 32) {
        __syncthreads();
        for (int idx = tid; idx < 64*32; idx += 256) {
            int t = idx >> 5, kk = idx & 31;
            Xs[t*33 + kk] = x[(long long)(tok0 + t)*EMB + k0 + kk];
        }
        for (int idx = tid; idx < 32*96; idx += 256) {
            int kk = idx / 96, c = idx % 96;
            int p = c >> 5, h = c & 31;
            const float* w1 = (p == 0) ? wk1 : ((p == 1) ? wq1 : wv1);
            Ws[kk*96 + c] = w1[(k0 + kk)*HALF + h];
        }
        __syncthreads();

#pragma unroll
        for (int kk = 0; kk < 32; kk++) {
            unsigned long long a2[4];
#pragma unroll
            for (int i = 0; i < 4; i++) {
                float a = Xs[(ty*4 + i)*33 + kk];
                a2[i] = pk2(a, a);
            }
            unsigned long long b2[3];
#pragma unroll
            for (int j = 0; j < 3; j++)
                b2[j] = *(const unsigned long long*)&Ws[kk*96 + tx*6 + 2*j];
#pragma unroll
            for (int i = 0; i < 4; i++)
#pragma unroll
                for (int j = 0; j < 3; j++)
                    acc2[i][j] = fma2(a2[i], b2[j], acc2[i][j]);
        }
    }
    __syncthreads();

#pragma unroll
    for (int i = 0; i < 4; i++) {
#pragma unroll
        for (int j = 0; j < 3; j++) {
            float lo, hi;
            upk2(acc2[i][j], lo, hi);
            int c0 = tx*6 + 2*j;
            int p0 = c0 >> 5, h0 = c0 & 31;
            const float* b1 = (p0 == 0) ? bk1 : ((p0 == 1) ? bq1 : bv1);
            lo = tanhf(lo + b1[h0]);
            hi = tanhf(hi + b1[h0 + 1]);
            Hs[(ty*4 + i)*96 + c0]     = lo;
            Hs[(ty*4 + i)*96 + c0 + 1] = hi;
        }
    }
    __syncthreads();

    for (int idx = tid; idx < 64*96; idx += 256) {
        int t = idx / 96, cp = idx % 96;
        int p = cp >> 5, hp = cp & 31;
        unsigned long long acc = 0ull;
#pragma unroll
        for (int j = 0; j < 32; j++) {
            float a = Hs[t*96 + p*32 + j];
            unsigned long long b = *(const unsigned long long*)&W2s[p*2048 + j*64 + 2*hp];
            acc = fma2(pk2(a, a), b, acc);
        }
        float lo, hi;
        upk2(acc, lo, hi);
        float* gout = (p == 0) ? g_K : ((p == 1) ? g_Q : g_V);
        long long o = (long long)(tok0 + t)*HD + 2*hp;
        gout[o]     = lo;
        gout[o + 1] = hi;
    }
}

// =========================================================================
// Causal flash attention v3: 4x4 register tiling, swizzled transposed tiles.
//   Block = 64 queries, 256 threads = (tq 0..15) x (tk 0..15).
//   QK: thread -> S[4 queries][4 keys]; per d: 1 LDS.128 Qt (broadcast) +
//       1 LDS.128 Kt -> 8 fma2.
//   PV: thread -> O[4 queries][4 dims]; per k: 1 LDS.128 Pt (broadcast) +
//       1 LDS.128 Vs -> 8 fma2.
//   Qt/Kt are [d][token] transposed with XOR block-swizzle on pitch-64 rows
//   (scalar transpose stores 2-way instead of 16-way conflicted).
//   Pt aliases Kt (3 syncthreads/tile). Smem = 3 x 16KB = 48KB exactly.
// =========================================================================
__global__ __launch_bounds__(256, 1) void attn_kernel(float* __restrict__ out)
{
    __shared__ __align__(16) float Qt[4096];    // [d][q] swizzled, prescaled
    __shared__ __align__(16) float KtPt[4096];  // [d][k] swizzled; later P[k][q] swizzled
    __shared__ __align__(16) float Vs[4096];    // [k][d] row-major

    const int tid = threadIdx.x;
    const int tq  = tid >> 4;
    const int tk  = tid & 15;
    const int tq4 = tq * 4;
    const int tk4 = tk * 4;
    const int bid = blockIdx.x;
    const int b   = bid & 7;
    const int qt  = 63 - (bid >> 3);            // heavy diagonal blocks first
    const long long tokbase = (long long)b * SLEN;
    const long long qbase   = (tokbase + (long long)qt*64) * HD;

    // ---- stage Qt: transpose + swizzle + prescale (once per block) ----
    {
        const float4* gq = (const float4*)(g_Q + qbase);
#pragma unroll
        for (int it = 0; it < 4; it++) {
            int idx = tid + it*256;            // 1024 float4 slots
            int r = idx >> 4, f = idx & 15;    // r = token, f = d-group
            float4 v = gq[idx];
            int colb = ((r & ~3) ^ ((f & 7) << 2)) + (r & 3);
            Qt[(4*f + 0)*64 + colb] = v.x * 0.125f;
            Qt[(4*f + 1)*64 + colb] = v.y * 0.125f;
            Qt[(4*f + 2)*64 + colb] = v.z * 0.125f;
            Qt[(4*f + 3)*64 + colb] = v.w * 0.125f;
        }
    }

    float m[4], l[4];
    unsigned long long o2[4][2];
#pragma unroll
    for (int i = 0; i < 4; i++) {
        m[i] = -1e30f; l[i] = 0.f;
        o2[i][0] = 0ull; o2[i][1] = 0ull;
    }

    for (int kt = 0; kt <= qt; kt++) {
        __syncthreads();   // A: prior PV reads of Pt/Vs complete (also covers Qt staging)
        {
            const long long base = (tokbase + (long long)kt*64) * HD;
            const float4* gk = (const float4*)(g_K + base);
            const float4* gv = (const float4*)(g_V + base);
#pragma unroll
            for (int it = 0; it < 4; it++) {
                int idx = tid + it*256;
                int r = idx >> 4, f = idx & 15;
                float4 kv = gk[idx];
                int colb = ((r & ~3) ^ ((f & 7) << 2)) + (r & 3);
                KtPt[(4*f + 0)*64 + colb] = kv.x;
                KtPt[(4*f + 1)*64 + colb] = kv.y;
                KtPt[(4*f + 2)*64 + colb] = kv.z;
                KtPt[(4*f + 3)*64 + colb] = kv.w;
                ((float4*)Vs)[idx] = gv[idx];
            }
        }
        __syncthreads();   // B: tiles staged

        // ---- QK: S[4q][4k] via outer products over d ----
        unsigned long long s2[4][2];
#pragma unroll
        for (int i = 0; i < 4; i++) { s2[i][0] = 0ull; s2[i][1] = 0ull; }

#pragma unroll 8
        for (int d = 0; d < 64; d++) {
            int sw = ((d >> 2) & 7) << 2;
            float4      qv = *(const float4*)     &Qt  [d*64 + (tq4 ^ sw)];
            ulonglong2  kv = *(const ulonglong2*) &KtPt[d*64 + (tk4 ^ sw)];
            unsigned long long q0 = pk2(qv.x, qv.x);
            unsigned long long q1 = pk2(qv.y, qv.y);
            unsigned long long q2r = pk2(qv.z, qv.z);
            unsigned long long q3 = pk2(qv.w, qv.w);
            s2[0][0] = fma2(q0,  kv.x, s2[0][0]);  s2[0][1] = fma2(q0,  kv.y, s2[0][1]);
            s2[1][0] = fma2(q1,  kv.x, s2[1][0]);  s2[1][1] = fma2(q1,  kv.y, s2[1][1]);
            s2[2][0] = fma2(q2r, kv.x, s2[2][0]);  s2[2][1] = fma2(q2r, kv.y, s2[2][1]);
            s2[3][0] = fma2(q3,  kv.x, s2[3][0]);  s2[3][1] = fma2(q3,  kv.y, s2[3][1]);
        }

        float s[4][4];
#pragma unroll
        for (int i = 0; i < 4; i++) {
            upk2(s2[i][0], s[i][0], s[i][1]);
            upk2(s2[i][1], s[i][2], s[i][3]);
        }

        if (kt == qt) {    // diagonal tile mask (uniform branch)
#pragma unroll
            for (int i = 0; i < 4; i++)
#pragma unroll
                for (int j = 0; j < 4; j++)
                    if (tk4 + j > tq4 + i) s[i][j] = -1e30f;
        }

        // ---- online softmax; row stats over the 16 tk lanes ----
#pragma unroll
        for (int i = 0; i < 4; i++) {
            float mn = fmaxf(fmaxf(s[i][0], s[i][1]), fmaxf(s[i][2], s[i][3]));
            mn = fmaxf(mn, m[i]);
            mn = fmaxf(mn, __shfl_xor_sync(0xffffffffu, mn, 1));
            mn = fmaxf(mn, __shfl_xor_sync(0xffffffffu, mn, 2));
            mn = fmaxf(mn, __shfl_xor_sync(0xffffffffu, mn, 4));
            mn = fmaxf(mn, __shfl_xor_sync(0xffffffffu, mn, 8));
            float c = __expf(m[i] - mn);
            m[i] = mn;
            float p0 = __expf(s[i][0] - mn);
            float p1 = __expf(s[i][1] - mn);
            float p2 = __expf(s[i][2] - mn);
            float p3 = __expf(s[i][3] - mn);
            l[i] = l[i]*c + (p0 + p1) + (p2 + p3);
            unsigned long long cc = pk2(c, c);
            o2[i][0] = mul2(o2[i][0], cc);
            o2[i][1] = mul2(o2[i][1], cc);
            s[i][0] = p0; s[i][1] = p1; s[i][2] = p2; s[i][3] = p3;
        }

        __syncthreads();   // C: all warps done reading Kt -> safe to overwrite with P
        {
            int sw = (tk & 7) << 2;            // swz(k) with k>>2 == tk
#pragma unroll
            for (int j = 0; j < 4; j++) {
                *(float4*)&KtPt[(tk4 + j)*64 + (tq4 ^ sw)] =
                    make_float4(s[0][j], s[1][j], s[2][j], s[3][j]);
            }
        }
        __syncwarp();      // Pt columns read by same half-warp that wrote them

        // ---- PV: O[4q][4d] over all 64 keys ----
#pragma unroll 8
        for (int k = 0; k < 64; k++) {
            int sw = ((k >> 2) & 7) << 2;
            float4     pv = *(const float4*)     &KtPt[k*64 + (tq4 ^ sw)];
            ulonglong2 vv = *(const ulonglong2*) &Vs  [k*64 + tk4];
            unsigned long long p0 = pk2(pv.x, pv.x);
            unsigned long long p1 = pk2(pv.y, pv.y);
            unsigned long long p2 = pk2(pv.z, pv.z);
            unsigned long long p3 = pk2(pv.w, pv.w);
            o2[0][0] = fma2(p0, vv.x, o2[0][0]);  o2[0][1] = fma2(p0, vv.y, o2[0][1]);
            o2[1][0] = fma2(p1, vv.x, o2[1][0]);  o2[1][1] = fma2(p1, vv.y, o2[1][1]);
            o2[2][0] = fma2(p2, vv.x, o2[2][0]);  o2[2][1] = fma2(p2, vv.y, o2[2][1]);
            o2[3][0] = fma2(p3, vv.x, o2[3][0]);  o2[3][1] = fma2(p3, vv.y, o2[3][1]);
        }
    }

    // ---- merge l over tk lanes; write O ----
#pragma unroll
    for (int i = 0; i < 4; i++) {
        float lt = l[i];
        lt += __shfl_xor_sync(0xffffffffu, lt, 1);
        lt += __shfl_xor_sync(0xffffffffu, lt, 2);
        lt += __shfl_xor_sync(0xffffffffu, lt, 4);
        lt += __shfl_xor_sync(0xffffffffu, lt, 8);
        float inv = 1.0f / lt;
        unsigned long long ii = pk2(inv, inv);
        unsigned long long v0 = mul2(o2[i][0], ii);
        unsigned long long v1 = mul2(o2[i][1], ii);
        float a, bb, c, d;
        upk2(v0, a, bb);
        upk2(v1, c, d);
        *(float4*)(out + qbase + (long long)(tq4 + i)*HD + tk4) = make_float4(a, bb, c, d);
    }
}

extern "C" void kernel_launch(void* const* d_in, const int* in_sizes, int n_in,
                              void* d_out, int out_size)
{
    const float* x   = (const float*)d_in[0];
    const float* wk1 = (const float*)d_in[1];
    const float* bk1 = (const float*)d_in[2];
    const float* wk2 = (const float*)d_in[3];
    const float* wq1 = (const float*)d_in[4];
    const float* bq1 = (const float*)d_in[5];
    const float* wq2 = (const float*)d_in[6];
    const float* wv1 = (const float*)d_in[7];
    const float* bv1 = (const float*)d_in[8];
    const float* wv2 = (const float*)d_in[9];

    proj_kernel<<<TOK/64, 256>>>(x, wk1, bk1, wk2, wq1, bq1, wq2, wv1, bv1, wv2);
    attn_kernel<<<NBATCH * (SLEN/64), 256>>>((float*)d_out);
}